// round 10
// baseline (speedup 1.0000x reference)
#include <cuda_runtime.h>
#include <math_constants.h>

// Problem constants (match reference_code)
#define NUM_TOKENS_C   32768
#define NUM_BLOCKS_C   1024
#define BLOCK_SIZE_C   128
#define NUM_KV_HEADS_C 8
#define HEAD_DIM_C     128
#define SLOT_ELEMS     (NUM_KV_HEADS_C * HEAD_DIM_C)     // 1024 floats = 4KB per slot
#define NUM_SLOTS      (NUM_BLOCKS_C * BLOCK_SIZE_C)     // 131072 slots
#define FP8_MAX_C      240.0f

#define WARPS_PER_CTA  8
#define FUSED_THREADS  (WARPS_PER_CTA * 32)              // 256
#define FUSED_CTAS     (NUM_SLOTS / WARPS_PER_CTA)       // 16384 (one warp per slot)
#define SCATTER_CTAS   (NUM_TOKENS_C / FUSED_THREADS)    // 128

// Scratch (allocation-free __device__ globals, zero-initialized at load).
// g_slot_map: slot -> packed (slot+1 | token). Self-validating: an entry is
//   valid for slot s iff its high word == s+1; untouched (zero) entries never
//   validate. Slots are unique per token, so any validating entry is correct.
// g_arrive / g_done: intra-kernel gate + end-of-launch reset. The last CTA
//   (done == FUSED_CTAS) can only exist after every CTA passed the gate, so
//   resetting both counters there is race-free; every launch starts at (0,0).
__device__ unsigned long long g_slot_map[NUM_SLOTS];
__device__ unsigned int g_arrive;
__device__ unsigned int g_done;

// Single fused kernel:
//   phase 1 (CTAs 0..127): scatter 256 map entries each, fence, arrive.
//   gate: thread 0 of every CTA spins (volatile, coherent) until all 128
//         scatter CTAs arrived; wave-1 (>=5 CTAs/SM * 148 SMs) always
//         contains CTAs 0..127, so no deadlock. Then fence + bar.
//   phase 2 (all CTAs): one warp per 4KB slot — 1 COHERENT (__ldcg, L2) map
//         lookup (NOT __ldg: the .nc path may return stale data for lines
//         written by other CTAs within the same launch — that was R9's bug),
//         8 front-batched float4 streaming loads (MLP_p1=8), branchless
//         scale+clamp, 8 streaming stores.
__global__ void __launch_bounds__(FUSED_THREADS) fused_kvcache_kernel(
    const float4* __restrict__ inp,     // [NUM_TOKENS, 256] float4
    const float4* __restrict__ cache,   // [NUM_SLOTS, 256] float4
    const int*    __restrict__ bidx,    // [NUM_TOKENS]
    const int*    __restrict__ boff,    // [NUM_TOKENS]
    const float*  __restrict__ p_scale_in,
    const float*  __restrict__ p_scale_out,
    float4* __restrict__ out)           // [NUM_SLOTS, 256] float4
{
    const int cta  = blockIdx.x;
    const int tid  = threadIdx.x;

    // ── Phase 1: inline scatter (CTAs 0..127 only) ─────────────────────────
    if (cta < SCATTER_CTAS) {
        const int t = cta * FUSED_THREADS + tid;          // 0..32767
        const int slot = __ldg(&bidx[t]) * BLOCK_SIZE_C + __ldg(&boff[t]);
        const unsigned long long e =
            ((unsigned long long)(unsigned)(slot + 1) << 32) |
            (unsigned long long)(unsigned)t;
        __stcg(&g_slot_map[slot], e);                     // store to L2 (coherence point)
        __threadfence();                                  // publish map entries
        __syncthreads();                                  // all 256 stores done
        if (tid == 0) atomicAdd(&g_arrive, 1u);
    }

    // ── Gate: wait for all scatter CTAs of THIS launch ─────────────────────
    if (tid == 0) {
        while (*(volatile unsigned int*)&g_arrive < SCATTER_CTAS)
            __nanosleep(128);
        __threadfence();                                  // acquire side
    }
    __syncthreads();                                      // propagate to CTA

    // ── Phase 2: bulk pass, one warp per slot ──────────────────────────────
    const int slot = cta * WARPS_PER_CTA + (tid >> 5);
    const int lane = tid & 31;

    // Coherent L2 read of the map entry (see comment above).
    const unsigned long long e = __ldcg(&g_slot_map[slot]);
    const int token = (int)(unsigned)(e & 0xffffffffull);
    const bool valid = ((int)(unsigned)(e >> 32) == slot + 1) &&
                       ((unsigned)token < (unsigned)NUM_TOKENS_C);

    const float so = __ldg(p_scale_out);
    const float si = __ldg(p_scale_in);

    // Branchless unification:
    //   valid:   clamp(v/si, +-240) * so == clamp(v*(so/si), lo, hi)
    //   invalid: v * so               == clamp(v*so, -inf, +inf)
    const float m  = valid ? (so / si) : so;
    const float b  = FP8_MAX_C * so;
    const float lo = valid ? fminf(-b, b) : -CUDART_INF_F;
    const float hi = valid ? fmaxf(-b, b) :  CUDART_INF_F;

    const float4* src = valid ? (inp + ((long)token << 8)) : (cache + ((long)slot << 8));
    float4* dst = out + ((long)slot << 8);

    float4 v[8];
    #pragma unroll
    for (int j = 0; j < 8; j++)
        v[j] = __ldcs(src + lane + j * 32);

    #pragma unroll
    for (int j = 0; j < 8; j++) {
        v[j].x = fminf(fmaxf(v[j].x * m, lo), hi);
        v[j].y = fminf(fmaxf(v[j].y * m, lo), hi);
        v[j].z = fminf(fmaxf(v[j].z * m, lo), hi);
        v[j].w = fminf(fmaxf(v[j].w * m, lo), hi);
    }

    #pragma unroll
    for (int j = 0; j < 8; j++)
        __stcs(dst + lane + j * 32, v[j]);

    // ── Epilogue: last CTA resets gate state for the next launch ───────────
    if (tid == 0) {
        if (atomicAdd(&g_done, 1u) == FUSED_CTAS - 1u) {
            g_arrive = 0u;
            g_done   = 0u;
            __threadfence();
        }
    }
}

extern "C" void kernel_launch(void* const* d_in, const int* in_sizes, int n_in,
                              void* d_out, int out_size) {
    // metadata order: input, cache, block_indices, block_offset, scale_input, scale_output
    const float4* inp   = (const float4*)d_in[0];
    const float4* cache = (const float4*)d_in[1];
    const int*    bidx  = (const int*)  d_in[2];
    const int*    boff  = (const int*)  d_in[3];
    const float*  s_in  = (const float*)d_in[4];
    const float*  s_out = (const float*)d_in[5];
    float4* out = (float4*)d_out;

    // Single launch: scatter + gate + bulk pass fused in one grid.
    fused_kvcache_kernel<<<FUSED_CTAS, FUSED_THREADS>>>(inp, cache, bidx, boff,
                                                        s_in, s_out, out);
}